// round 16
// baseline (speedup 1.0000x reference)
#include <cuda_runtime.h>

// Problem constants (fixed by the dataset)
#define NN      262144            // nodes per tree (2^18)
#define NT      12                // B*C trees
#define HWPX    1048576           // H*W (2^20)
#define T0      2048              // exactly-solved prefix per tree (2^11)
#define TOTAL   (NT * NN)
#define TPG     4                 // trees per gather group

#define S2_LO   32768
#define S3_LO   131072
#define S2_TREE ((S3_LO - S2_LO) / 256)     // 384 s2 blocks/tree
#define S3_TREE ((NN - S3_LO) / 256)        // 512 s3 blocks/tree
#define GB_TREE (HWPX / 4 / 256)            // 1024 gather blocks/tree
#define GB_GRP  (GB_TREE * TPG)             // 4096
#define S3_GRP  (S3_TREE * TPG)             // 2048

// Scratch (allocation-free rule: __device__ globals)
__device__ float4 g_node[TOTAL];   // {c0,c1,c2,parent-as-float-bits}
__device__ float4 g_F[TOTAL];      // final {f0,f1,f2,_}

__device__ __forceinline__ float sigmoidf_(float x) {
    return 1.0f / (1.0f + expf(-x));
}

// ---------------------------------------------------------------------------
// Contrib math for one quad (4 nodes): returns 4 packed node records.
// ---------------------------------------------------------------------------
__device__ __forceinline__ void contrib_quad(
        const float4* __restrict__ attrs4, const float4* __restrict__ residue4,
        const int4* __restrict__ parent4, size_t q,
        float w0, float w10, float w11, float w2,
        float B0, float B1, float B2, float4 rec[4]) {
    float4 A0 = __ldcs(&attrs4[3 * q + 0]);   // a0[0] a1[0] a2[0] a0[1]
    float4 A1 = __ldcs(&attrs4[3 * q + 1]);   // a1[1] a2[1] a0[2] a1[2]
    float4 A2 = __ldcs(&attrs4[3 * q + 2]);   // a2[2] a0[3] a1[3] a2[3]
    float4 R  = __ldcs(&residue4[q]);
    int4   P  = __ldcs(&parent4[q]);

    float a0[4] = {A0.x, A0.w, A1.z, A2.y};
    float a1[4] = {A0.y, A1.x, A1.w, A2.z};
    float a2[4] = {A0.z, A1.y, A2.x, A2.w};
    float r[4]  = {R.x, R.y, R.z, R.w};
    int   p[4]  = {P.x, P.y, P.z, P.w};

#pragma unroll
    for (int k = 0; k < 4; k++) {
        float c0 = sigmoidf_(fmaf(a0[k], w0, B0)) * r[k];
        float c1 = sigmoidf_(fmaf(a2[k], w11, fmaf(a1[k], w10, B1))) * r[k];
        float c2 = sigmoidf_(fmaf(a1[k], w2, B2)) * r[k];
        rec[k] = make_float4(c0, c1, c2, __int_as_float(p[k]));
    }
}

// ---------------------------------------------------------------------------
// K1: contrib (all nodes) + exact prefix solve for [0,T0) (12 special blocks).
// ---------------------------------------------------------------------------
__global__ void k_contrib_prefix(const float4* __restrict__ attrs4,
                                 const float4* __restrict__ residue4,
                                 const int4*  __restrict__ parent4,
                                 const float* __restrict__ W0,
                                 const float* __restrict__ W1,
                                 const float* __restrict__ W2,
                                 const float* __restrict__ b0,
                                 const float* __restrict__ b1,
                                 const float* __restrict__ b2) {
    __shared__ float4 sm[T0];

    const float w0  = __ldg(W0);
    const float w10 = __ldg(&W1[0]);
    const float w11 = __ldg(&W1[1]);
    const float w2  = __ldg(W2);
    const float B0 = __ldg(b0), B1 = __ldg(b1), B2 = __ldg(b2);

    if (blockIdx.x >= NT) {
        // ---- normal contrib block ----
        size_t q = (size_t)(blockIdx.x - NT) * blockDim.x + threadIdx.x;
        float4 rec[4];
        contrib_quad(attrs4, residue4, parent4, q,
                     w0, w10, w11, w2, B0, B1, B2, rec);
        float4* outp = g_node + 4 * q;
#pragma unroll
        for (int k = 0; k < 4; k++) outp[k] = rec[k];
        return;
    }

    // ---- special block: contrib for [0,T0) + Wyllie prefix ----
    const int tree = blockIdx.x;
    const int tid = threadIdx.x;

#pragma unroll
    for (int c = 0; c < 2; c++) {
        int lq = tid + c * 256;                       // local quad 0..511
        size_t q = (size_t)tree * (NN / 4) + lq;
        float4 rec[4];
        contrib_quad(attrs4, residue4, parent4, q,
                     w0, w10, w11, w2, B0, B1, B2, rec);
        float4* outp = g_node + 4 * q;
#pragma unroll
        for (int k = 0; k < 4; k++) {
            outp[k] = rec[k];
            sm[4 * lq + k] = rec[k];
        }
    }
    __syncthreads();

    for (int r = 0; r < 11; r++) {
        float4 tmp[8];
#pragma unroll
        for (int k = 0; k < 8; k++) {
            int e = tid + k * 256;
            float4 v = sm[e];
            int p = __float_as_int(v.w);
            if (p < T0) {
                float4 o = sm[p];
                v.x += o.x; v.y += o.y; v.z += o.z; v.w = o.w;
            }
            tmp[k] = v;
        }
        __syncthreads();
#pragma unroll
        for (int k = 0; k < 8; k++) sm[tid + k * 256] = tmp[k];
        __syncthreads();
    }

    float4* Fb = g_F + (size_t)tree * NN;
#pragma unroll
    for (int k = 0; k < 8; k++) {
        int e = tid + k * 256;
        float4 v = sm[e];
        Fb[e] = make_float4(v.x, v.y, v.z, 0.0f);
    }
}

// ---------------------------------------------------------------------------
// Cascade body: finalize F for node n of `tree`; everything below `start`
// is already final in g_F.
// ---------------------------------------------------------------------------
__device__ __forceinline__ void cascade_body(int tree, int start, int n) {
    const float4* nb = g_node + (size_t)tree * NN;
    float4*       Fb = g_F    + (size_t)tree * NN;

    float4 v = __ldg(&nb[n]);
    float ax = v.x, ay = v.y, az = v.z;
    int p = __float_as_int(v.w);

    while (p >= start) {
        float4 u = __ldg(&nb[p]);
        ax += u.x; ay += u.y; az += u.z;
        p = __float_as_int(u.w);
    }
    float4 f = __ldg(&Fb[p]);
    Fb[n] = make_float4(ax + f.x, ay + f.y, az + f.z, 0.0f);
}

// Full-width cascade kernel: all trees (gridDim.y = NT)
__global__ void k_cascade(int start) {
    const int tree = blockIdx.y;
    const int n = start + blockIdx.x * blockDim.x + threadIdx.x;
    cascade_body(tree, start, n);
}

// ---------------------------------------------------------------------------
// K3: s2 [32768,131072) all trees, MIXED with s3'(G0): [131072,262144) of
// trees 0..3 walked with start=32768 (needs only F<32768, final after K2 —
// all blocks runnable at launch). s2 blocks take the low bids.
// ---------------------------------------------------------------------------
__global__ void k_s2_mix(void) {
    int bid = blockIdx.x;

    if (bid < S2_TREE * NT) {
        const int tree = bid / S2_TREE;
        const int n = S2_LO + (bid % S2_TREE) * 256 + threadIdx.x;
        cascade_body(tree, S2_LO, n);
        return;
    }
    bid -= S2_TREE * NT;
    {   // s3' of group 0, deep walk to <32768
        const int tree = bid / S3_TREE;                  // 0..3
        const int n = S3_LO + (bid % S3_TREE) * 256 + threadIdx.x;
        cascade_body(tree, S2_LO, n);
    }
}

// ---------------------------------------------------------------------------
// Gather body: 4 pixels/thread for `tree`; one 16B gather serves all 3
// output channels; coalesced float4 stores per channel plane.
// ---------------------------------------------------------------------------
__device__ __forceinline__ void gather_body(int tree, int lt,
                                            const int4* __restrict__ pix4,
                                            float* __restrict__ out) {
    int4 nd = __ldcs(&pix4[(size_t)tree * (HWPX / 4) + lt]);

    const float4* Fb = g_F + (size_t)tree * NN;
    float4 F0 = __ldg(&Fb[nd.x]);
    float4 F1 = __ldg(&Fb[nd.y]);
    float4 F2 = __ldg(&Fb[nd.z]);
    float4 F3 = __ldg(&Fb[nd.w]);

    float* o = out + (size_t)tree * 3 * HWPX + 4 * (size_t)lt;
    __stcs((float4*)(o),            make_float4(F0.x, F1.x, F2.x, F3.x));
    __stcs((float4*)(o + HWPX),     make_float4(F0.y, F1.y, F2.y, F3.y));
    __stcs((float4*)(o + 2 * HWPX), make_float4(F0.z, F1.z, F2.z, F3.z));
}

// ---------------------------------------------------------------------------
// Mixed-role kernel: gather group `gbase` + s3 stage (start=131072) of group
// `s3base`. All blocks runnable at launch. Gather blocks take the low bids.
// ---------------------------------------------------------------------------
__global__ void k_mix(int gbase, int s3base,
                      const int4* __restrict__ pix4,
                      float* __restrict__ out) {
    int bid = blockIdx.x;

    if (bid < GB_GRP) {
        const int tree = gbase + bid / GB_TREE;
        const int lt = (bid % GB_TREE) * 256 + threadIdx.x;
        gather_body(tree, lt, pix4, out);
        return;
    }
    bid -= GB_GRP;
    {
        const int tree = s3base + bid / S3_TREE;
        const int n = S3_LO + (bid % S3_TREE) * 256 + threadIdx.x;
        cascade_body(tree, S3_LO, n);
    }
}

// ---------------------------------------------------------------------------
// Entry point — 6 serial launches:
//   K1 contrib+prefix (merged)
//   K2 s01 [2048,32768) all trees
//   K3 s2 [32768,131072) all trees || s3'(G0) deep-walk (start=32768)
//   K4 gather(G0) || s3(G1);  K5 gather(G1) || s3(G2);  K6 gather(G2)
// Inputs: attrs, residue, W0, W1, W2, b0, b1, b2, parent, pixel_node
// ---------------------------------------------------------------------------
extern "C" void kernel_launch(void* const* d_in, const int* in_sizes, int n_in,
                              void* d_out, int out_size) {
    const float4* attrs4   = (const float4*)d_in[0];
    const float4* residue4 = (const float4*)d_in[1];
    const float* W0        = (const float*)d_in[2];
    const float* W1        = (const float*)d_in[3];
    const float* W2        = (const float*)d_in[4];
    const float* b0        = (const float*)d_in[5];
    const float* b1        = (const float*)d_in[6];
    const float* b2        = (const float*)d_in[7];
    const int4*  parent4   = (const int4*)d_in[8];
    const int4*  pix4      = (const int4*)d_in[9];
    float*       out       = (float*)d_out;

    // K1: contrib (all trees) + prefix solve (12 special blocks, bids 0..11)
    k_contrib_prefix<<<NT + TOTAL / 4 / 256, 256>>>(attrs4, residue4, parent4,
                                                    W0, W1, W2, b0, b1, b2);
    // K2: s01 [2048, 32768), all trees
    {
        dim3 grid((S2_LO - 2048) / 256, NT);
        k_cascade<<<grid, 256>>>(2048);
    }
    // K3: s2 (all trees) || s3'(G0) deep-walk
    k_s2_mix<<<S2_TREE * NT + S3_TREE * TPG, 256>>>();

    // K4: gather(G0) || s3(G1)
    k_mix<<<GB_GRP + S3_GRP, 256>>>(0, TPG, pix4, out);
    // K5: gather(G1) || s3(G2)
    k_mix<<<GB_GRP + S3_GRP, 256>>>(TPG, 2 * TPG, pix4, out);
    // K6: gather(G2), pure
    k_mix<<<GB_GRP, 256>>>(2 * TPG, 0 /*unused*/, pix4, out);
}

// round 17
// speedup vs baseline: 1.5198x; 1.5198x over previous
#include <cuda_runtime.h>

// Problem constants (fixed by the dataset)
#define NN      262144            // nodes per tree (2^18)
#define NT      12                // B*C trees
#define HWPX    1048576           // H*W (2^20)
#define T0      2048              // exactly-solved prefix per tree (2^11)
#define TOTAL   (NT * NN)
#define TPG     4                 // trees per gather group
#define NGRP    (NT / TPG)        // 3 groups

// Tail stage boundaries
#define S3_LO   131072
#define S3_HI   262144

// Blocks per tree for each role (256-thread blocks)
#define GB_TREE (HWPX / 4 / 256)            // 1024 gather blocks/tree
#define S3_TREE ((S3_HI - S3_LO) / 256)     // 512
#define GB_GRP  (GB_TREE * TPG)             // 4096
#define S3_GRP  (S3_TREE * TPG)             // 2048

// Scratch (allocation-free rule: __device__ globals)
__device__ float4 g_node[TOTAL];   // {c0,c1,c2,parent-as-float-bits}
__device__ float4 g_F[TOTAL];      // final {f0,f1,f2,_}

__device__ __forceinline__ float sigmoidf_(float x) {
    return 1.0f / (1.0f + expf(-x));
}

// ---------------------------------------------------------------------------
// Contrib math for one quad (4 nodes): returns 4 packed node records.
// ---------------------------------------------------------------------------
__device__ __forceinline__ void contrib_quad(
        const float4* __restrict__ attrs4, const float4* __restrict__ residue4,
        const int4* __restrict__ parent4, size_t q,
        float w0, float w10, float w11, float w2,
        float B0, float B1, float B2, float4 rec[4]) {
    float4 A0 = __ldcs(&attrs4[3 * q + 0]);   // a0[0] a1[0] a2[0] a0[1]
    float4 A1 = __ldcs(&attrs4[3 * q + 1]);   // a1[1] a2[1] a0[2] a1[2]
    float4 A2 = __ldcs(&attrs4[3 * q + 2]);   // a2[2] a0[3] a1[3] a2[3]
    float4 R  = __ldcs(&residue4[q]);
    int4   P  = __ldcs(&parent4[q]);

    float a0[4] = {A0.x, A0.w, A1.z, A2.y};
    float a1[4] = {A0.y, A1.x, A1.w, A2.z};
    float a2[4] = {A0.z, A1.y, A2.x, A2.w};
    float r[4]  = {R.x, R.y, R.z, R.w};
    int   p[4]  = {P.x, P.y, P.z, P.w};

#pragma unroll
    for (int k = 0; k < 4; k++) {
        float c0 = sigmoidf_(fmaf(a0[k], w0, B0)) * r[k];
        float c1 = sigmoidf_(fmaf(a2[k], w11, fmaf(a1[k], w10, B1))) * r[k];
        float c2 = sigmoidf_(fmaf(a1[k], w2, B2)) * r[k];
        rec[k] = make_float4(c0, c1, c2, __int_as_float(p[k]));
    }
}

// ---------------------------------------------------------------------------
// K1: contrib (all nodes) + exact prefix solve for [0,T0).
// Blocks 0..NT-1 (special): compute contribs for nodes [0,T0) of their tree,
//   run in-smem Wyllie jumping (11 rounds), write g_node AND g_F[0,T0).
// Blocks NT.. (normal): plain contrib for one quad-stripe (the [0,T0) quads
//   are written redundantly — identical bits, benign).
// Special blocks hide entirely under the DRAM-bound normal stream.
// ---------------------------------------------------------------------------
__global__ void k_contrib_prefix(const float4* __restrict__ attrs4,
                                 const float4* __restrict__ residue4,
                                 const int4*  __restrict__ parent4,
                                 const float* __restrict__ W0,
                                 const float* __restrict__ W1,
                                 const float* __restrict__ W2,
                                 const float* __restrict__ b0,
                                 const float* __restrict__ b1,
                                 const float* __restrict__ b2) {
    __shared__ float4 sm[T0];

    const float w0  = __ldg(W0);
    const float w10 = __ldg(&W1[0]);
    const float w11 = __ldg(&W1[1]);
    const float w2  = __ldg(W2);
    const float B0 = __ldg(b0), B1 = __ldg(b1), B2 = __ldg(b2);

    if (blockIdx.x >= NT) {
        // ---- normal contrib block ----
        size_t q = (size_t)(blockIdx.x - NT) * blockDim.x + threadIdx.x;
        float4 rec[4];
        contrib_quad(attrs4, residue4, parent4, q,
                     w0, w10, w11, w2, B0, B1, B2, rec);
        float4* outp = g_node + 4 * q;
#pragma unroll
        for (int k = 0; k < 4; k++) outp[k] = rec[k];
        return;
    }

    // ---- special block: contrib for [0,T0) + Wyllie prefix ----
    const int tree = blockIdx.x;
    const int tid = threadIdx.x;

#pragma unroll
    for (int c = 0; c < 2; c++) {
        int lq = tid + c * 256;                       // local quad 0..511
        size_t q = (size_t)tree * (NN / 4) + lq;
        float4 rec[4];
        contrib_quad(attrs4, residue4, parent4, q,
                     w0, w10, w11, w2, B0, B1, B2, rec);
        float4* outp = g_node + 4 * q;
#pragma unroll
        for (int k = 0; k < 4; k++) {
            outp[k] = rec[k];
            sm[4 * lq + k] = rec[k];
        }
    }
    __syncthreads();

    // Wyllie pointer jumping: 8 entries/thread, 11 rounds cover chains <= 2048.
    for (int r = 0; r < 11; r++) {
        float4 tmp[8];
#pragma unroll
        for (int k = 0; k < 8; k++) {
            int e = tid + k * 256;
            float4 v = sm[e];
            int p = __float_as_int(v.w);
            if (p < T0) {
                float4 o = sm[p];
                v.x += o.x; v.y += o.y; v.z += o.z; v.w = o.w;
            }
            tmp[k] = v;
        }
        __syncthreads();
#pragma unroll
        for (int k = 0; k < 8; k++) sm[tid + k * 256] = tmp[k];
        __syncthreads();
    }

    float4* Fb = g_F + (size_t)tree * NN;
#pragma unroll
    for (int k = 0; k < 8; k++) {
        int e = tid + k * 256;
        float4 v = sm[e];
        Fb[e] = make_float4(v.x, v.y, v.z, 0.0f);
    }
}

// ---------------------------------------------------------------------------
// Cascade body: finalize F for node n of `tree`; everything below `start`
// is already final in g_F.
// ---------------------------------------------------------------------------
__device__ __forceinline__ void cascade_body(int tree, int start, int n) {
    const float4* nb = g_node + (size_t)tree * NN;
    float4*       Fb = g_F    + (size_t)tree * NN;

    float4 v = __ldg(&nb[n]);
    float ax = v.x, ay = v.y, az = v.z;
    int p = __float_as_int(v.w);

    while (p >= start) {
        float4 u = __ldg(&nb[p]);
        ax += u.x; ay += u.y; az += u.z;
        p = __float_as_int(u.w);
    }
    float4 f = __ldg(&Fb[p]);
    Fb[n] = make_float4(ax + f.x, ay + f.y, az + f.z, 0.0f);
}

// Plain cascade kernel: all trees (gridDim.y = NT)
__global__ void k_cascade(int start) {
    const int tree = blockIdx.y;
    const int n = start + blockIdx.x * blockDim.x + threadIdx.x;
    cascade_body(tree, start, n);
}

// Group cascade kernel: trees [base, base+gridDim.y)
__global__ void k_cascade_grp(int base, int start) {
    const int tree = base + blockIdx.y;
    const int n = start + blockIdx.x * blockDim.x + threadIdx.x;
    cascade_body(tree, start, n);
}

// ---------------------------------------------------------------------------
// Gather body: 4 pixels/thread for `tree`; one 16B gather serves all 3
// output channels; coalesced float4 stores per channel plane.
// ---------------------------------------------------------------------------
__device__ __forceinline__ void gather_body(int tree, int lt,
                                            const int4* __restrict__ pix4,
                                            float* __restrict__ out) {
    int4 nd = __ldcs(&pix4[(size_t)tree * (HWPX / 4) + lt]);

    const float4* Fb = g_F + (size_t)tree * NN;
    float4 F0 = __ldg(&Fb[nd.x]);
    float4 F1 = __ldg(&Fb[nd.y]);
    float4 F2 = __ldg(&Fb[nd.z]);
    float4 F3 = __ldg(&Fb[nd.w]);

    float* o = out + (size_t)tree * 3 * HWPX + 4 * (size_t)lt;
    __stcs((float4*)(o),            make_float4(F0.x, F1.x, F2.x, F3.x));
    __stcs((float4*)(o + HWPX),     make_float4(F0.y, F1.y, F2.y, F3.y));
    __stcs((float4*)(o + 2 * HWPX), make_float4(F0.z, F1.z, F2.z, F3.z));
}

// ---------------------------------------------------------------------------
// Mixed-role kernel: gather group `gbase` + (optionally) s3 stage of group
// `s3base`. All blocks runnable at launch (deps completed in prior kernels).
// Gather blocks take the low bids so the long-pole work launches first.
// ---------------------------------------------------------------------------
__global__ void k_mix(int gbase, int s3base,
                      const int4* __restrict__ pix4,
                      float* __restrict__ out) {
    int bid = blockIdx.x;

    if (bid < GB_GRP) {
        const int tree = gbase + bid / GB_TREE;
        const int lt = (bid % GB_TREE) * 256 + threadIdx.x;
        gather_body(tree, lt, pix4, out);
        return;
    }
    bid -= GB_GRP;
    {
        const int tree = s3base + bid / S3_TREE;
        const int n = S3_LO + (bid % S3_TREE) * 256 + threadIdx.x;
        cascade_body(tree, S3_LO, n);
    }
}

// ---------------------------------------------------------------------------
// Entry point — 7 serial launches (verified-best configuration):
//   K1: contrib+prefix (merged)
//   K2: s01 [2048, 32768)  (merged s0+s1, start=2048 — depends only on K1)
//   K3: s2  [32768, 131072)
//   K4: s3 group 0 (pipeline head, shallow walk start=131072)
//   K5: gather(G0) || s3(G1);  K6: gather(G1) || s3(G2);  K7: gather(G2)
// Inputs: attrs, residue, W0, W1, W2, b0, b1, b2, parent, pixel_node
// ---------------------------------------------------------------------------
extern "C" void kernel_launch(void* const* d_in, const int* in_sizes, int n_in,
                              void* d_out, int out_size) {
    const float4* attrs4   = (const float4*)d_in[0];
    const float4* residue4 = (const float4*)d_in[1];
    const float* W0        = (const float*)d_in[2];
    const float* W1        = (const float*)d_in[3];
    const float* W2        = (const float*)d_in[4];
    const float* b0        = (const float*)d_in[5];
    const float* b1        = (const float*)d_in[6];
    const float* b2        = (const float*)d_in[7];
    const int4*  parent4   = (const int4*)d_in[8];
    const int4*  pix4      = (const int4*)d_in[9];
    float*       out       = (float*)d_out;

    // K1: contrib (all trees) + prefix solve (12 special blocks, bids 0..11)
    k_contrib_prefix<<<NT + TOTAL / 4 / 256, 256>>>(attrs4, residue4, parent4,
                                                    W0, W1, W2, b0, b1, b2);

    // K2: s01 [2048, 32768), start=2048 (walks to <2048, F there is final)
    {
        dim3 grid((32768 - 2048) / 256, NT);
        k_cascade<<<grid, 256>>>(2048);
    }
    // K3: s2 [32768, 131072)
    {
        dim3 grid((131072 - 32768) / 256, NT);
        k_cascade<<<grid, 256>>>(32768);
    }
    // K4: s3 [131072, 262144), group 0 only (unavoidable pipeline head)
    {
        dim3 grid(S3_TREE, TPG);
        k_cascade_grp<<<grid, 256>>>(0, S3_LO);
    }
    // K5: gather(G0) || s3(G1)
    k_mix<<<GB_GRP + S3_GRP, 256>>>(0, TPG, pix4, out);
    // K6: gather(G1) || s3(G2)
    k_mix<<<GB_GRP + S3_GRP, 256>>>(TPG, 2 * TPG, pix4, out);
    // K7: gather(G2), pure
    k_mix<<<GB_GRP, 256>>>(2 * TPG, 0 /*unused*/, pix4, out);
}